// round 6
// baseline (speedup 1.0000x reference)
#include <cuda_runtime.h>
#include <cuda_bf16.h>
#include <cstdint>
#include <math.h>

typedef unsigned int u32;

#define D 128
#define HID 64

// Per-node projections in bf16: P[i][0:64] = embeds[i] @ W1[0:128,:]
//                               P[i][64:128] = embeds[i] @ W1[128:256,:]
__device__ __nv_bfloat16 g_Pb[(size_t)50000 * 2 * HID];
// Constant part: embeds[n] @ W1[256:384,:] + b1  (fp32)
__device__ __align__(16) float g_cvec[HID];

// ---------------------------------------------------------------------------
// cp.async helpers
// ---------------------------------------------------------------------------
__device__ __forceinline__ void cpa16(u32 saddr, const void* g, int bytes) {
    asm volatile("cp.async.cg.shared.global [%0], [%1], 16, %2;"
                 :: "r"(saddr), "l"(g), "r"(bytes));
}
__device__ __forceinline__ void cpa_commit() {
    asm volatile("cp.async.commit_group;");
}
template <int N>
__device__ __forceinline__ void cpa_wait() {
    asm volatile("cp.async.wait_group %0;" :: "n"(N));
}

// ---------------------------------------------------------------------------
// K1: tensor-core proj (+ folded cvec in the last block).
// P = embeds @ [W1a | W1b]  (M=n_nodes, N=128, K=128)
// mma.sync.m16n8k8.tf32 (raw fp32 bits; HW truncates to tf32).
// 256 thr = 8 warps (2x4), warp tile 64x32.
// K pipelined in chunks of 16 via cp.async double buffering.
// ---------------------------------------------------------------------------
#define KCHUNK 16
#define APITCH 20      // (20g+tg)%32 distinct over 32 lanes -> conflict-free
#define BPITCH 136     // (8tg+g)%32 distinct -> conflict-free

__global__ __launch_bounds__(256) void proj_mma(const float* __restrict__ embeds,
                                                const float* __restrict__ W1,
                                                const float* __restrict__ b1,
                                                const int* __restrict__ n_ptr,
                                                int n_nodes) {
    __shared__ u32 As[2][128 * APITCH];   // 2 x 10240 B
    __shared__ u32 Bs[2][KCHUNK * BPITCH];// 2 x  8704 B

    const int tid = threadIdx.x;

    // ---- last block: compute cvec (runs concurrently with proj blocks) ----
    if (blockIdx.x == gridDim.x - 1) {
        float* red = (float*)As;          // reuse smem
        int t = tid >> 6;
        int j = tid & 63;
        int n = n_ptr[0];
        const float* e = embeds + (size_t)n * D;
        float acc = 0.f;
#pragma unroll 8
        for (int k = t * 32; k < t * 32 + 32; k++)
            acc = fmaf(e[k], W1[(2 * D + k) * HID + j], acc);
        red[t * HID + j] = acc;
        __syncthreads();
        if (t == 0)
            g_cvec[j] = b1[j] + red[0 * HID + j] + red[1 * HID + j] +
                        red[2 * HID + j] + red[3 * HID + j];
        return;
    }

    const int warpid = tid >> 5;
    const int lane   = tid & 31;
    const int g      = lane >> 2;
    const int tg     = lane & 3;
    const int warp_m = warpid & 1;
    const int warp_n = warpid >> 1;
    const int rowBase = blockIdx.x * 128;

    u32 sAs = (u32)__cvta_generic_to_shared(&As[0][0]);
    u32 sBs = (u32)__cvta_generic_to_shared(&Bs[0][0]);

    // per-thread staging coords (2 float4 each for A and B)
    // A: f = tid + i*256 ; r = f>>2 ; k4 = (f&3)*4
    // B: f = tid + i*256 ; kk = f>>5 ; n4 = (f&31)*4
    auto stage = [&](int buf, int kc) {
#pragma unroll
        for (int i = 0; i < 2; i++) {
            int f  = tid + i * 256;
            int r  = f >> 2;
            int k4 = (f & 3) * 4;
            int gr = rowBase + r;
            int bytes = (gr < n_nodes) ? 16 : 0;
            const float* gp = &embeds[(size_t)(gr < n_nodes ? gr : 0) * D + kc + k4];
            cpa16(sAs + (buf * 128 * APITCH + r * APITCH + k4) * 4, gp, bytes);
        }
#pragma unroll
        for (int i = 0; i < 2; i++) {
            int f  = tid + i * 256;
            int kk = f >> 5;
            int n4 = (f & 31) * 4;
            int kg = kc + kk;
            const float* gp = (n4 < HID) ? &W1[kg * HID + n4]
                                         : &W1[(D + kg) * HID + (n4 - HID)];
            cpa16(sBs + (buf * KCHUNK * BPITCH + kk * BPITCH + n4) * 4, gp, 16);
        }
        cpa_commit();
    };

    float c[4][4][4];
#pragma unroll
    for (int m = 0; m < 4; m++)
#pragma unroll
        for (int n = 0; n < 4; n++)
#pragma unroll
            for (int r = 0; r < 4; r++) c[m][n][r] = 0.f;

    stage(0, 0);

    const int NITER = D / KCHUNK;   // 8
    for (int it = 0; it < NITER; it++) {
        int buf = it & 1;
        if (it < NITER - 1) stage(buf ^ 1, (it + 1) * KCHUNK);
        if (it < NITER - 1) cpa_wait<1>(); else cpa_wait<0>();
        __syncthreads();

        const u32* A = &As[buf][0];
        const u32* B = &Bs[buf][0];
#pragma unroll
        for (int ks = 0; ks < KCHUNK; ks += 8) {
            u32 a[4][4], b[4][2];
#pragma unroll
            for (int m = 0; m < 4; m++) {
                int r0 = warp_m * 64 + m * 16;
                a[m][0] = A[(r0 + g)     * APITCH + ks + tg];
                a[m][1] = A[(r0 + g + 8) * APITCH + ks + tg];
                a[m][2] = A[(r0 + g)     * APITCH + ks + tg + 4];
                a[m][3] = A[(r0 + g + 8) * APITCH + ks + tg + 4];
            }
#pragma unroll
            for (int n = 0; n < 4; n++) {
                int c0 = warp_n * 32 + n * 8 + g;
                b[n][0] = B[(ks + tg)     * BPITCH + c0];
                b[n][1] = B[(ks + tg + 4) * BPITCH + c0];
            }
#pragma unroll
            for (int m = 0; m < 4; m++)
#pragma unroll
                for (int n = 0; n < 4; n++) {
                    asm volatile(
                        "mma.sync.aligned.m16n8k8.row.col.f32.tf32.tf32.f32 "
                        "{%0,%1,%2,%3}, {%4,%5,%6,%7}, {%8,%9}, {%0,%1,%2,%3};"
                        : "+f"(c[m][n][0]), "+f"(c[m][n][1]),
                          "+f"(c[m][n][2]), "+f"(c[m][n][3])
                        : "r"(a[m][0]), "r"(a[m][1]), "r"(a[m][2]), "r"(a[m][3]),
                          "r"(b[n][0]), "r"(b[n][1]));
                }
        }
        __syncthreads();
    }

    // epilogue: rows g, g+8; cols 2*tg, 2*tg+1 -> bf16
#pragma unroll
    for (int m = 0; m < 4; m++) {
        int r0 = rowBase + warp_m * 64 + m * 16;
#pragma unroll
        for (int n = 0; n < 4; n++) {
            int col = warp_n * 32 + n * 8 + tg * 2;
            int ra = r0 + g, rb = r0 + g + 8;
            if (ra < n_nodes)
                *(__nv_bfloat162*)&g_Pb[(size_t)ra * 128 + col] =
                    __floats2bfloat162_rn(c[m][n][0], c[m][n][1]);
            if (rb < n_nodes)
                *(__nv_bfloat162*)&g_Pb[(size_t)rb * 128 + col] =
                    __floats2bfloat162_rn(c[m][n][2], c[m][n][3]);
        }
    }
}

// ---------------------------------------------------------------------------
// K2: 4 edges per warp (8 lanes each). 16B bf16 gathers; fast-math tail
// executed once per warp for all 4 edges (lanes 0/8/16/24 predicated on).
// ---------------------------------------------------------------------------
__global__ __launch_bounds__(256) void edge_kernel(const float* __restrict__ W2,
                            const float* __restrict__ b2,
                            const float* __restrict__ u,
                            const int* __restrict__ src,
                            const int* __restrict__ dst,
                            float* __restrict__ out,
                            int E) {
    int gidx = blockIdx.x * blockDim.x + threadIdx.x;
    int warp = gidx >> 5;
    int lane = threadIdx.x & 31;
    int q = lane >> 3;          // quarter id 0..3
    int l = lane & 7;           // lane within quarter
    int e = warp * 4 + q;
    if (e >= E) return;

    int s = __ldg(&src[e]);
    int d = __ldg(&dst[e]);
    const uint4* Ps = (const uint4*)(g_Pb + (size_t)s * 128);       // 64 bf16
    const uint4* Pd = (const uint4*)(g_Pb + (size_t)d * 128 + 64);  // 64 bf16
    uint4 pu = Ps[l];
    uint4 du = Pd[l];
    float4 c0 = *(const float4*)&g_cvec[8 * l];
    float4 c1 = *(const float4*)&g_cvec[8 * l + 4];
    float4 w0 = *(const float4*)&W2[8 * l];
    float4 w1 = *(const float4*)&W2[8 * l + 4];

    float2 pA = __bfloat1622float2(*(const __nv_bfloat162*)&pu.x);
    float2 pB = __bfloat1622float2(*(const __nv_bfloat162*)&pu.y);
    float2 pC = __bfloat1622float2(*(const __nv_bfloat162*)&pu.z);
    float2 pD = __bfloat1622float2(*(const __nv_bfloat162*)&pu.w);
    float2 dA = __bfloat1622float2(*(const __nv_bfloat162*)&du.x);
    float2 dB = __bfloat1622float2(*(const __nv_bfloat162*)&du.y);
    float2 dC = __bfloat1622float2(*(const __nv_bfloat162*)&du.z);
    float2 dD = __bfloat1622float2(*(const __nv_bfloat162*)&du.w);

    float h0 = fmaxf(pA.x + dA.x + c0.x, 0.f);
    float h1 = fmaxf(pA.y + dA.y + c0.y, 0.f);
    float h2 = fmaxf(pB.x + dB.x + c0.z, 0.f);
    float h3 = fmaxf(pB.y + dB.y + c0.w, 0.f);
    float h4 = fmaxf(pC.x + dC.x + c1.x, 0.f);
    float h5 = fmaxf(pC.y + dC.y + c1.y, 0.f);
    float h6 = fmaxf(pD.x + dD.x + c1.z, 0.f);
    float h7 = fmaxf(pD.y + dD.y + c1.w, 0.f);

    float acc = h0 * w0.x;
    acc = fmaf(h1, w0.y, acc);
    acc = fmaf(h2, w0.z, acc);
    acc = fmaf(h3, w0.w, acc);
    acc = fmaf(h4, w1.x, acc);
    acc = fmaf(h5, w1.y, acc);
    acc = fmaf(h6, w1.z, acc);
    acc = fmaf(h7, w1.w, acc);

    acc += __shfl_xor_sync(0xffffffffu, acc, 4);
    acc += __shfl_xor_sync(0xffffffffu, acc, 2);
    acc += __shfl_xor_sync(0xffffffffu, acc, 1);

    if (l == 0) {
        float sw = acc + __ldg(&b2[0]);
        float eps = fmaf(-0.9998f, __ldg(&u[e]), 0.9999f);
        // gate/TEMP = (ln2/5) * (log2(eps) - log2(1-eps))
        float gate5 = 0.13862944f * (__log2f(eps) - __log2f(1.f - eps));
        float z = gate5 + sw * 0.2f;                 // TEMP = 5
        out[e] = 1.f / (1.f + __expf(-z));
    }
}

// ---------------------------------------------------------------------------
// Inputs (metadata order): embeds, W1, b1, W2, b2, u, src, dst, n
// ---------------------------------------------------------------------------
extern "C" void kernel_launch(void* const* d_in, const int* in_sizes, int n_in,
                              void* d_out, int out_size) {
    const float* embeds = (const float*)d_in[0];
    const float* W1     = (const float*)d_in[1];
    const float* b1     = (const float*)d_in[2];
    const float* W2     = (const float*)d_in[3];
    const float* b2     = (const float*)d_in[4];
    const float* u      = (const float*)d_in[5];
    const int*   src    = (const int*)d_in[6];
    const int*   dst    = (const int*)d_in[7];
    const int*   n_ptr  = (const int*)d_in[8];

    int n_nodes = in_sizes[0] / D;
    int E       = in_sizes[6];

    int nb = (n_nodes + 127) / 128;
    proj_mma<<<nb + 1, 256>>>(embeds, W1, b1, n_ptr, n_nodes);

    int warps = (E + 3) / 4;
    int blocks = (warps * 32 + 255) / 256;
    edge_kernel<<<blocks, 256>>>(W2, b2, u, src, dst, (float*)d_out, E);
}